// round 3
// baseline (speedup 1.0000x reference)
#include <cuda_runtime.h>
#include <cstdint>
#include <cstddef>

// Problem dims
#define BB 256
#define TT 256
#define II 512
#define HH 1024
#define KTOT (II + HH)        // 1536

#define NCTA 128
#define NTHREADS 256
#define HALF_CTAS 64          // CTAs per independent batch-half

// K decomposition: 96 chunks of 16; each CTA owns 12 chunks (K=192)
#define KCHUNK 16
#define NCHUNKS_TOTAL (KTOT / KCHUNK)   // 96
#define CH_PER_CTA 12

// smem tile stride (floats): 16 data + 4 pad -> bank-conflict-free frag reads,
// rows 80B so 16B-aligned for cp.async
#define SST 20

// ---------------- persistent device state ----------------
__device__ float    g_h[BB * HH];                    // recurrent state, fp32
__device__ float    g_part[2 * 8 * 8 * 128 * 128];   // split-K partials (8 MB)
__device__ unsigned g_cnt[2];
__device__ unsigned g_gen[2];

// ---------------- grid barrier (per half, sense-reversing) ----------------
__device__ __forceinline__ void gbar(int half) {
    __threadfence();           // make this thread's global writes visible
    __syncthreads();
    if (threadIdx.x == 0) {
        volatile unsigned* vg = (volatile unsigned*)&g_gen[half];
        unsigned g = *vg;
        unsigned old = atomicAdd(&g_cnt[half], 1u);
        if (old == HALF_CTAS - 1) {
            g_cnt[half] = 0;
            __threadfence();
            *vg = g + 1;
        } else {
            while (*vg == g) { __nanosleep(32); }
        }
    }
    __syncthreads();
}

// ---------------- async chunk loader ----------------
// Loads A tile (128 x 16 of [x_t | h]) and W tile (128 x 16 of [Wx_t | Wh_t])
// for K-chunk j into smem (stride SST). Uses cp.async.cg (L2-only: required for
// correctness since g_h is written by other SMs; L1 is not coherent).
__device__ __forceinline__ void load_chunk16(
    int j, int t, int mhalf, int nblk,
    const float* __restrict__ inp, const float* __restrict__ Wx,
    const float* __restrict__ Wh, float* sA, float* sW, int tid)
{
    int k0  = j * KCHUNK;
    bool isx = (k0 < II);
    int koff = isx ? k0 : (k0 - II);
#pragma unroll
    for (int it = 0; it < 2; it++) {
        int v   = tid + NTHREADS * it;      // 0..511
        int row = v >> 2;                   // 0..127
        int c4  = (v & 3) * 4;              // 0,4,8,12

        const float* asrc;
        int gm = mhalf * 128 + row;
        if (isx) asrc = inp + (size_t)gm * (TT * II) + (size_t)t * II + koff + c4;
        else     asrc = g_h + (size_t)gm * HH + koff + c4;
        uint32_t ad = (uint32_t)__cvta_generic_to_shared(sA + row * SST + c4);
        asm volatile("cp.async.cg.shared.global [%0], [%1], 16;" :: "r"(ad), "l"(asrc));

        const float* wsrc;
        int ng = nblk * 128 + row;
        if (isx) wsrc = Wx + ((size_t)t * HH + ng) * II + koff + c4;
        else     wsrc = Wh + ((size_t)t * HH + ng) * HH + koff + c4;
        uint32_t wd = (uint32_t)__cvta_generic_to_shared(sW + row * SST + c4);
        asm volatile("cp.async.cg.shared.global [%0], [%1], 16;" :: "r"(wd), "l"(wsrc));
    }
    asm volatile("cp.async.commit_group;");
}

// ---------------- tf32 mma over one 16-wide K chunk ----------------
// warp tile: 32 (M) x 64 (N) -> 2 x 8 m16n8k8 tiles
__device__ __forceinline__ void mma_chunk16(
    const float* __restrict__ sA, const float* __restrict__ sW,
    float (&acc)[2][8][4], int g, int tg, int wm, int wn)
{
#pragma unroll
    for (int kk = 0; kk < KCHUNK; kk += 8) {
        uint32_t ua[2][4];
#pragma unroll
        for (int s = 0; s < 2; s++) {
            int base = (wm * 32 + s * 16 + g) * SST + kk + tg;
            float f0 = sA[base];
            float f1 = sA[base + 8 * SST];
            float f2 = sA[base + 4];
            float f3 = sA[base + 8 * SST + 4];
            asm volatile("cvt.rna.tf32.f32 %0, %1;" : "=r"(ua[s][0]) : "f"(f0));
            asm volatile("cvt.rna.tf32.f32 %0, %1;" : "=r"(ua[s][1]) : "f"(f1));
            asm volatile("cvt.rna.tf32.f32 %0, %1;" : "=r"(ua[s][2]) : "f"(f2));
            asm volatile("cvt.rna.tf32.f32 %0, %1;" : "=r"(ua[s][3]) : "f"(f3));
        }
#pragma unroll
        for (int u = 0; u < 8; u++) {
            int nb = (wn * 64 + u * 8 + g) * SST + kk + tg;
            float fb0 = sW[nb];
            float fb1 = sW[nb + 4];
            uint32_t ub0, ub1;
            asm volatile("cvt.rna.tf32.f32 %0, %1;" : "=r"(ub0) : "f"(fb0));
            asm volatile("cvt.rna.tf32.f32 %0, %1;" : "=r"(ub1) : "f"(fb1));
#pragma unroll
            for (int s = 0; s < 2; s++) {
                asm volatile(
                    "mma.sync.aligned.m16n8k8.row.col.f32.tf32.tf32.f32 "
                    "{%0,%1,%2,%3},{%4,%5,%6,%7},{%8,%9},{%0,%1,%2,%3};"
                    : "+f"(acc[s][u][0]), "+f"(acc[s][u][1]),
                      "+f"(acc[s][u][2]), "+f"(acc[s][u][3])
                    : "r"(ua[s][0]), "r"(ua[s][1]), "r"(ua[s][2]), "r"(ua[s][3]),
                      "r"(ub0), "r"(ub1));
            }
        }
    }
}

// ---------------- persistent RNN kernel ----------------
__global__ void __launch_bounds__(NTHREADS, 1)
SequenceModelPadded_kernel(
    const float* __restrict__ inp,        // (B,T,I)
    const void* __restrict__ slen_raw,    // (B,) int64 OR int32 (JAX x64 flag!)
    const float* __restrict__ Wx,         // (T,H,I)
    const float* __restrict__ Wh,         // (T,H,H)
    const float* __restrict__ bias,       // (T,H)
    const float* __restrict__ Wout,       // (O,H) = (1,H)
    const float* __restrict__ bout,       // (O,)
    float* __restrict__ out)              // (B,O) = (B,1)
{
    __shared__ float sA[2][128 * SST];
    __shared__ float sW[2][128 * SST];
    __shared__ int   s_is64;

    int tid = threadIdx.x;
    int bx  = blockIdx.x;
    int mhalf = bx >> 6;        // 0/1: batch rows [0,128) / [128,256)
    int lh    = bx & 63;        // id within half
    int nblk  = lh >> 3;        // 0..7: output cols [nblk*128, +128)
    int ks    = lh & 7;         // 0..7: K split

    int lane = tid & 31, warp = tid >> 5;
    int wm = warp & 3, wn = warp >> 2;       // warp tile position
    int g  = lane >> 2, tg = lane & 3;       // mma groupID / tid-in-group

    // ---- detect seq_lengths dtype (int64 vs int32) ----
    // If int64: words at odd indices are high halves of 128 non-negative
    // lengths -> all zero. If int32: odd words are random lengths in [0,T)
    // -> OR is nonzero. Scans only words 0..255 (in-bounds for both dtypes).
    if (tid == 0) {
        const unsigned* w = (const unsigned*)slen_raw;
        unsigned z = 0;
        for (int i = 1; i < 256; i += 2) z |= __ldg(&w[i]);
        s_is64 = (z == 0) ? 1 : 0;
    }
    __syncthreads();
    const int is64 = s_is64;

    // ---- init h = 0 for this half ----
    for (int e = lh * NTHREADS + tid; e < 128 * HH; e += HALF_CTAS * NTHREADS)
        g_h[mhalf * 128 * HH + e] = 0.f;
    gbar(mhalf);

    int jbase = ks * CH_PER_CTA;

    for (int t = 0; t < TT; t++) {
        // ---- GEMM phase: partial = A[128 x 192] * W[128 x 192]^T ----
        float acc[2][8][4];
#pragma unroll
        for (int s = 0; s < 2; s++)
#pragma unroll
            for (int u = 0; u < 8; u++)
#pragma unroll
                for (int q = 0; q < 4; q++) acc[s][u][q] = 0.f;

        load_chunk16(jbase, t, mhalf, nblk, inp, Wx, Wh, sA[0], sW[0], tid);
        for (int jj = 0; jj < CH_PER_CTA; jj++) {
            if (jj < CH_PER_CTA - 1) {
                int nb2 = (jj + 1) & 1;
                load_chunk16(jbase + jj + 1, t, mhalf, nblk, inp, Wx, Wh,
                             sA[nb2], sW[nb2], tid);
                asm volatile("cp.async.wait_group 1;");
            } else {
                asm volatile("cp.async.wait_group 0;");
            }
            __syncthreads();
            mma_chunk16(sA[jj & 1], sW[jj & 1], acc, g, tg, wm, wn);
            __syncthreads();
        }

        // ---- store split-K partial tile (128 x 128 fp32) ----
        {
            float* P = g_part + (((mhalf * 8 + ks) * 8 + nblk) << 14);
#pragma unroll
            for (int s = 0; s < 2; s++)
#pragma unroll
                for (int u = 0; u < 8; u++) {
                    int r = wm * 32 + s * 16 + g;
                    int c = wn * 64 + u * 8 + 2 * tg;
                    P[r * 128 + c]           = acc[s][u][0];
                    P[r * 128 + c + 1]       = acc[s][u][1];
                    P[(r + 8) * 128 + c]     = acc[s][u][2];
                    P[(r + 8) * 128 + c + 1] = acc[s][u][3];
                }
        }
        gbar(mhalf);

        // ---- reduce split-K + bias, tanh, mask-update h ----
        for (int e = lh * NTHREADS + tid; e < 128 * HH; e += HALF_CTAS * NTHREADS) {
            int r = e >> 10;            // local batch row 0..127
            int c = e & 1023;           // hidden col
            int nb = c >> 7, cl = c & 127;
            float pre = __ldg(&bias[t * HH + c]);
#pragma unroll
            for (int k2 = 0; k2 < 8; k2++)
                pre += __ldcg(&g_part[(((mhalf * 8 + k2) * 8 + nb) << 14) + r * 128 + cl]);
            int gm = mhalf * 128 + r;
            long long L;
            if (is64) L = __ldg(&((const long long*)slen_raw)[gm]);
            else      L = (long long)__ldg(&((const int*)slen_raw)[gm]);
            if ((long long)t < L)
                g_h[(size_t)gm * HH + c] = tanhf(pre);
            // else: keep old h (no write)
        }
        gbar(mhalf);
    }

    // ---- output: out[b] = h[b,:] . Wout + bout[0] (2 rows per CTA) ----
    float* red = &sA[0][0];
#pragma unroll
    for (int rr = 0; rr < 2; rr++) {
        int gr = mhalf * 128 + lh * 2 + rr;
        float p = 0.f;
        for (int c = tid; c < HH; c += NTHREADS)
            p += __ldcg(&g_h[(size_t)gr * HH + c]) * __ldg(&Wout[c]);
        red[tid] = p;
        __syncthreads();
        for (int s = 128; s > 0; s >>= 1) {
            if (tid < s) red[tid] += red[tid + s];
            __syncthreads();
        }
        if (tid == 0) out[gr] = red[0] + __ldg(&bout[0]);
        __syncthreads();
    }
}

extern "C" void kernel_launch(void* const* d_in, const int* in_sizes, int n_in,
                              void* d_out, int out_size) {
    (void)in_sizes; (void)n_in; (void)out_size;
    const float* inp  = (const float*)d_in[0];
    const void*  slen = (const void*)d_in[1];
    const float* Wx   = (const float*)d_in[2];
    const float* Wh   = (const float*)d_in[3];
    const float* bias = (const float*)d_in[4];
    const float* Wout = (const float*)d_in[5];
    const float* bout = (const float*)d_in[6];
    float*       out  = (float*)d_out;

    SequenceModelPadded_kernel<<<NCTA, NTHREADS>>>(
        inp, slen, Wx, Wh, bias, Wout, bout, out);
}

// round 5
// speedup vs baseline: 1.2314x; 1.2314x over previous
#include <cuda_runtime.h>
#include <cstdint>
#include <cstddef>

#define BB 256
#define TT 256
#define II 512
#define HH 1024

#define NTHREADS 256
#define NCTA 128
#define HALFC 64

// ---- dynamic smem layout (float offsets) ----
#define F_SA      0
#define F_SA_BUF  (128*36)          // loop A chunk (128 x 32, stride 36)
#define F_PA_BUF  (256*36)          // precompute A chunk (256 x 32)
#define F_SW      (2*F_PA_BUF)      // 18432
#define F_SW_BUF  (64*260)          // loop W slice (64 x 256, stride 260)
#define F_PW_BUF  (128*36)          // precompute W chunk (128 x 32)
#define F_XP      (F_SW + 2*F_SW_BUF)   // 51712
#define F_XP_BUF  (128*16)
#define F_BI      (F_XP + 2*F_XP_BUF)   // 55808
#define F_BI_BUF  16
#define SMEM_FLOATS (F_BI + 2*F_BI_BUF) // 55840
#define SMEM_BYTES  (SMEM_FLOATS*4)     // 223360 bytes

// ---- persistent device state ----
__device__ float    g_h[BB * HH];
__device__ float    g_part[128 * 128 * 64];            // 4 MB split-K partials
__device__ float    g_xpart[(size_t)TT * BB * HH];     // 268 MB precomputed x@Wx^T
__device__ unsigned g_cnt[3];
__device__ unsigned g_gen[3];

// ---- grid barrier (sense-reversing, acquire on waiter) ----
__device__ __forceinline__ void gbar(int idx, unsigned count) {
    __threadfence();               // release: my global writes visible
    __syncthreads();
    if (threadIdx.x == 0) {
        volatile unsigned* vg = (volatile unsigned*)&g_gen[idx];
        unsigned g = *vg;
        unsigned old = atomicAdd(&g_cnt[idx], 1u);
        if (old == count - 1) {
            g_cnt[idx] = 0;
            __threadfence();
            *vg = g + 1;
        } else {
            while (*vg == g) { __nanosleep(32); }
            __threadfence();       // acquire: order subsequent reads after flag
        }
    }
    __syncthreads();
}

// ---- small helpers ----
__device__ __forceinline__ void cpa(float* dst, const float* src) {
    uint32_t d = (uint32_t)__cvta_generic_to_shared(dst);
    asm volatile("cp.async.cg.shared.global [%0], [%1], 16;" :: "r"(d), "l"(src));
}
#define CPCOMMIT() asm volatile("cp.async.commit_group;")
#define CPWAIT(n)  asm volatile("cp.async.wait_group %0;" :: "n"(n))

__device__ __forceinline__ uint32_t f2tf(float f) {
    uint32_t u; asm volatile("cvt.rna.tf32.f32 %0, %1;" : "=r"(u) : "f"(f)); return u;
}
__device__ __forceinline__ void mma8(float* c, uint32_t a0, uint32_t a1,
                                     uint32_t a2, uint32_t a3,
                                     uint32_t b0, uint32_t b1) {
    asm volatile(
        "mma.sync.aligned.m16n8k8.row.col.f32.tf32.tf32.f32 "
        "{%0,%1,%2,%3},{%4,%5,%6,%7},{%8,%9},{%0,%1,%2,%3};"
        : "+f"(c[0]), "+f"(c[1]), "+f"(c[2]), "+f"(c[3])
        : "r"(a0), "r"(a1), "r"(a2), "r"(a3), "r"(b0), "r"(b1));
}

// ---- persistent kernel ----
__global__ void __launch_bounds__(NTHREADS, 1)
SequenceModelPadded_kernel(
    const float* __restrict__ inp,        // (B,T,I)
    const void*  __restrict__ slen_raw,   // (B,) int64 OR int32
    const float* __restrict__ Wx,         // (T,H,I)
    const float* __restrict__ Wh,         // (T,H,H)
    const float* __restrict__ bias,       // (T,H)
    const float* __restrict__ Wout,       // (1,H)
    const float* __restrict__ bout,       // (1,)
    float* __restrict__ out)              // (B,1)
{
    extern __shared__ float sm[];

    int tid  = threadIdx.x;
    int bx   = blockIdx.x;
    int half = bx >> 6;          // batch half
    int lh   = bx & 63;          // id within half
    int nblk = lh >> 2;          // 0..15  (N tile of 64 cols)
    int ks   = lh & 3;           // 0..3   (K split of 256)

    int lane = tid & 31, warp = tid >> 5;
    int wm = warp & 3, wn = warp >> 2;   // 4 x 2 warp grid
    int g  = lane >> 2, tg = lane & 3;

    // ---- seq_lengths dtype sniff (int64 high words all zero) ----
    __shared__ int s_is64;
    if (tid == 0) {
        const unsigned* w = (const unsigned*)slen_raw;
        unsigned z = 0;
        for (int i = 1; i < 256; i += 2) z |= __ldg(&w[i]);
        s_is64 = (z == 0) ? 1 : 0;
    }
    __syncthreads();
    const int is64 = s_is64;

    // ---- h = 0 ----
    for (int e = tid; e < 2048; e += NTHREADS) g_h[bx * 2048 + e] = 0.f;

    // ============================================================
    // PROLOGUE: g_xpart[t,b,:] = x[b,t,:] @ Wx[t]^T  (parallel, no barriers)
    // Each CTA owns t = bx and t = bx+128. Tile M=256 x N=128, K=512.
    // ============================================================
    for (int rep = 0; rep < 2; rep++) {
        int t = bx + rep * 128;
        for (int nt = 0; nt < 8; nt++) {
            float acc[4][8][4];
#pragma unroll
            for (int s = 0; s < 4; s++)
#pragma unroll
                for (int u = 0; u < 8; u++)
#pragma unroll
                    for (int q = 0; q < 4; q++) acc[s][u][q] = 0.f;

            {   // chunk 0
                float* pa = sm + F_SA;
                float* pw = sm + F_SW;
#pragma unroll
                for (int it = 0; it < 8; it++) {
                    int v = tid + NTHREADS * it; int row = v >> 3, seg = v & 7;
                    cpa(pa + row * 36 + seg * 4,
                        inp + (size_t)row * (TT * II) + (size_t)t * II + seg * 4);
                }
#pragma unroll
                for (int it = 0; it < 4; it++) {
                    int v = tid + NTHREADS * it; int row = v >> 3, seg = v & 7;
                    cpa(pw + row * 36 + seg * 4,
                        Wx + ((size_t)t * HH + nt * 128 + row) * II + seg * 4);
                }
                CPCOMMIT();
            }
            for (int ch = 0; ch < 16; ch++) {
                if (ch < 15) {
                    int nb = (ch + 1) & 1;
                    float* pa = sm + F_SA + nb * F_PA_BUF;
                    float* pw = sm + F_SW + nb * F_PW_BUF;
                    int ko = (ch + 1) * 32;
#pragma unroll
                    for (int it = 0; it < 8; it++) {
                        int v = tid + NTHREADS * it; int row = v >> 3, seg = v & 7;
                        cpa(pa + row * 36 + seg * 4,
                            inp + (size_t)row * (TT * II) + (size_t)t * II + ko + seg * 4);
                    }
#pragma unroll
                    for (int it = 0; it < 4; it++) {
                        int v = tid + NTHREADS * it; int row = v >> 3, seg = v & 7;
                        cpa(pw + row * 36 + seg * 4,
                            Wx + ((size_t)t * HH + nt * 128 + row) * II + ko + seg * 4);
                    }
                    CPCOMMIT();
                    CPWAIT(1);
                } else {
                    CPWAIT(0);
                }
                __syncthreads();
                const float* pa = sm + F_SA + (ch & 1) * F_PA_BUF;
                const float* pw = sm + F_SW + (ch & 1) * F_PW_BUF;
#pragma unroll
                for (int kk = 0; kk < 4; kk++) {
                    uint32_t ua[4][4];
#pragma unroll
                    for (int s = 0; s < 4; s++) {
                        int base = (wm * 64 + s * 16 + g) * 36 + kk * 8 + tg;
                        ua[s][0] = f2tf(pa[base]);
                        ua[s][1] = f2tf(pa[base + 8 * 36]);
                        ua[s][2] = f2tf(pa[base + 4]);
                        ua[s][3] = f2tf(pa[base + 8 * 36 + 4]);
                    }
#pragma unroll
                    for (int u = 0; u < 8; u++) {
                        int wb = (wn * 64 + u * 8 + g) * 36 + kk * 8 + tg;
                        uint32_t b0 = f2tf(pw[wb]);
                        uint32_t b1 = f2tf(pw[wb + 4]);
#pragma unroll
                        for (int s = 0; s < 4; s++)
                            mma8(acc[s][u], ua[s][0], ua[s][1], ua[s][2], ua[s][3], b0, b1);
                    }
                }
                __syncthreads();
            }
#pragma unroll
            for (int s = 0; s < 4; s++)
#pragma unroll
                for (int u = 0; u < 8; u++) {
                    int r = wm * 64 + s * 16 + g;
                    int c = nt * 128 + wn * 64 + u * 8 + 2 * tg;
                    *(float2*)(g_xpart + ((size_t)t * BB + r) * HH + c) =
                        make_float2(acc[s][u][0], acc[s][u][1]);
                    *(float2*)(g_xpart + ((size_t)t * BB + r + 8) * HH + c) =
                        make_float2(acc[s][u][2], acc[s][u][3]);
                }
        }
    }

    gbar(2, NCTA);   // xpart + h-init globally visible

    // ============================================================
    // RECURRENT LOOP
    // ============================================================
    {   // prefetch step-0 W slice + xpart + bias into buffer 0
        float* ws = sm + F_SW;
#pragma unroll
        for (int it = 0; it < 16; it++) {
            int v = tid + NTHREADS * it; int row = v >> 6, seg = v & 63;
            cpa(ws + row * 260 + seg * 4,
                Wh + ((size_t)nblk * 64 + row) * HH + ks * 256 + seg * 4);
        }
        float* xps = sm + F_XP;
#pragma unroll
        for (int it = 0; it < 2; it++) {
            int v = tid + NTHREADS * it; int row = v >> 2, seg = v & 3;
            cpa(xps + row * 16 + seg * 4,
                g_xpart + ((size_t)half * 128 + row) * HH + lh * 16 + seg * 4);
        }
        if (tid < 4)
            cpa(sm + F_BI + tid * 4, bias + lh * 16 + tid * 4);
        CPCOMMIT();
    }

    for (int t = 0; t < TT; t++) {
        int cur = t & 1;
        const float* ws = sm + F_SW + cur * F_SW_BUF;

        float acc[2][4][4];
#pragma unroll
        for (int s = 0; s < 2; s++)
#pragma unroll
            for (int u = 0; u < 4; u++)
#pragma unroll
                for (int q = 0; q < 4; q++) acc[s][u][q] = 0.f;

        {   // A chunk 0
            float* pa = sm + F_SA;
            int ko = ks * 256;
#pragma unroll
            for (int it = 0; it < 4; it++) {
                int v = tid + NTHREADS * it; int row = v >> 3, seg = v & 7;
                cpa(pa + row * 36 + seg * 4,
                    g_h + (size_t)(half * 128 + row) * HH + ko + seg * 4);
            }
            CPCOMMIT();
        }
        for (int j = 0; j < 8; j++) {
            if (j < 7) {
                float* pa = sm + F_SA + ((j + 1) & 1) * F_SA_BUF;
                int ko = ks * 256 + (j + 1) * 32;
#pragma unroll
                for (int it = 0; it < 4; it++) {
                    int v = tid + NTHREADS * it; int row = v >> 3, seg = v & 7;
                    cpa(pa + row * 36 + seg * 4,
                        g_h + (size_t)(half * 128 + row) * HH + ko + seg * 4);
                }
                CPCOMMIT();
                CPWAIT(1);
            } else {
                CPWAIT(0);
            }
            __syncthreads();
            const float* pa = sm + F_SA + (j & 1) * F_SA_BUF;
#pragma unroll
            for (int kk = 0; kk < 4; kk++) {
                uint32_t ua[2][4];
#pragma unroll
                for (int s = 0; s < 2; s++) {
                    int base = (wm * 32 + s * 16 + g) * 36 + kk * 8 + tg;
                    ua[s][0] = f2tf(pa[base]);
                    ua[s][1] = f2tf(pa[base + 8 * 36]);
                    ua[s][2] = f2tf(pa[base + 4]);
                    ua[s][3] = f2tf(pa[base + 8 * 36 + 4]);
                }
#pragma unroll
                for (int u = 0; u < 4; u++) {
                    int wb = (wn * 32 + u * 8 + g) * 260 + j * 32 + kk * 8 + tg;
                    uint32_t b0 = f2tf(ws[wb]);
                    uint32_t b1 = f2tf(ws[wb + 4]);
#pragma unroll
                    for (int s = 0; s < 2; s++)
                        mma8(acc[s][u], ua[s][0], ua[s][1], ua[s][2], ua[s][3], b0, b1);
                }
            }
            __syncthreads();
        }

        {   // prefetch next step's W slice + xpart + bias
            int tn = (t + 1 < TT) ? (t + 1) : 0;
            int nb = (t + 1) & 1;
            float* wsn = sm + F_SW + nb * F_SW_BUF;
#pragma unroll
            for (int it = 0; it < 16; it++) {
                int v = tid + NTHREADS * it; int row = v >> 6, seg = v & 63;
                cpa(wsn + row * 260 + seg * 4,
                    Wh + ((size_t)tn * HH + nblk * 64 + row) * HH + ks * 256 + seg * 4);
            }
            float* xps = sm + F_XP + nb * F_XP_BUF;
#pragma unroll
            for (int it = 0; it < 2; it++) {
                int v = tid + NTHREADS * it; int row = v >> 2, seg = v & 3;
                cpa(xps + row * 16 + seg * 4,
                    g_xpart + ((size_t)tn * BB + half * 128 + row) * HH + lh * 16 + seg * 4);
            }
            if (tid < 4)
                cpa(sm + F_BI + nb * F_BI_BUF + tid * 4,
                    bias + (size_t)tn * HH + lh * 16 + tid * 4);
            CPCOMMIT();
        }

        {   // store split-K partial (128 x 64)
            float* P = g_part + (size_t)(half * 64 + lh) * 8192;
#pragma unroll
            for (int s = 0; s < 2; s++)
#pragma unroll
                for (int u = 0; u < 4; u++) {
                    int r = wm * 32 + s * 16 + g;
                    int c = wn * 32 + u * 8 + 2 * tg;
                    *(float2*)&P[r * 64 + c]       = make_float2(acc[s][u][0], acc[s][u][1]);
                    *(float2*)&P[(r + 8) * 64 + c] = make_float2(acc[s][u][2], acc[s][u][3]);
                }
        }
        gbar(half, HALFC);

        {   // reduce 4 partials + xpart + bias -> tanh -> masked h write
            int r   = tid >> 1;
            int c8  = (tid & 1) * 8;
            int cg_ = lh * 16 + c8;
            int nb4 = (cg_ >> 6) * 4;
            int cl0 = cg_ & 63;
            float v[8];
#pragma unroll
            for (int q = 0; q < 8; q++) v[q] = 0.f;
#pragma unroll
            for (int ksp = 0; ksp < 4; ksp++) {
                const float4* p = (const float4*)&g_part[
                    (size_t)(half * 64 + nb4 + ksp) * 8192 + r * 64 + cl0];
                float4 a = __ldcg(p);
                float4 b = __ldcg(p + 1);
                v[0] += a.x; v[1] += a.y; v[2] += a.z; v[3] += a.w;
                v[4] += b.x; v[5] += b.y; v[6] += b.z; v[7] += b.w;
            }
            const float* xps = sm + F_XP + cur * F_XP_BUF + r * 16 + c8;
            const float* bs  = sm + F_BI + cur * F_BI_BUF + c8;
#pragma unroll
            for (int q = 0; q < 8; q++) v[q] = tanhf(v[q] + xps[q] + bs[q]);

            int gm = half * 128 + r;
            long long L = is64 ? __ldg(&((const long long*)slen_raw)[gm])
                               : (long long)__ldg(&((const int*)slen_raw)[gm]);
            if ((long long)t < L) {
                float4* hp = (float4*)(g_h + (size_t)gm * HH + cg_);
                hp[0] = make_float4(v[0], v[1], v[2], v[3]);
                hp[1] = make_float4(v[4], v[5], v[6], v[7]);
            }
        }
        gbar(half, HALFC);
    }

    // ---- output: out[b] = h[b,:] . Wout + bout ----
    float* red = sm;   // reuse smem
#pragma unroll
    for (int rr = 0; rr < 2; rr++) {
        int gr = half * 128 + lh * 2 + rr;
        float p = 0.f;
        for (int c = tid; c < HH; c += NTHREADS)
            p += __ldcg(&g_h[(size_t)gr * HH + c]) * __ldg(&Wout[c]);
        red[tid] = p;
        __syncthreads();
        for (int s = 128; s > 0; s >>= 1) {
            if (tid < s) red[tid] += red[tid + s];
            __syncthreads();
        }
        if (tid == 0) out[gr] = red[0] + __ldg(&bout[0]);
        __syncthreads();
    }
}

extern "C" void kernel_launch(void* const* d_in, const int* in_sizes, int n_in,
                              void* d_out, int out_size) {
    (void)in_sizes; (void)n_in; (void)out_size;
    const float* inp  = (const float*)d_in[0];
    const void*  slen = (const void*)d_in[1];
    const float* Wx   = (const float*)d_in[2];
    const float* Wh   = (const float*)d_in[3];
    const float* bias = (const float*)d_in[4];
    const float* Wout = (const float*)d_in[5];
    const float* bout = (const float*)d_in[6];
    float*       out  = (float*)d_out;

    static int s_attr_done = 0;
    if (!s_attr_done) {
        cudaFuncSetAttribute(SequenceModelPadded_kernel,
                             cudaFuncAttributeMaxDynamicSharedMemorySize, SMEM_BYTES);
        s_attr_done = 1;
    }
    SequenceModelPadded_kernel<<<NCTA, NTHREADS, SMEM_BYTES>>>(
        inp, slen, Wx, Wh, bias, Wout, bout, out);
}

// round 6
// speedup vs baseline: 1.2913x; 1.0487x over previous
#include <cuda_runtime.h>
#include <cstdint>
#include <cstddef>

#define BB 256
#define TT 256
#define II 512
#define HH 1024

#define NTHREADS 256
#define NCTA 128
#define HALFC 64

// ---- dynamic smem layout (float offsets) ----
#define F_SA      0
#define F_SA_BUF  (128*36)          // loop A chunk (128 x 32, stride 36)
#define F_PA_BUF  (256*36)          // precompute A chunk (256 x 32)
#define F_SW      (2*F_PA_BUF)      // 18432
#define F_SW_BUF  (64*260)          // loop W slice (64 x 256, stride 260)
#define F_PW_BUF  (128*36)          // precompute W chunk (128 x 32)
#define F_XP      (F_SW + 2*F_SW_BUF)   // 51712
#define F_XP_BUF  (128*16)
#define F_BI      (F_XP + 2*F_XP_BUF)   // 55808
#define F_BI_BUF  16
#define SMEM_FLOATS (F_BI + 2*F_BI_BUF) // 55840
#define SMEM_BYTES  (SMEM_FLOATS*4)     // 223360 bytes (+4KB static = ok < 227KB)

// ---- persistent device state ----
__device__ float    g_h[BB * HH];                      // h, stored tf32-rounded
__device__ float    g_part[128 * 128 * 64];            // 4 MB split-K partials
__device__ float    g_xpart[(size_t)TT * BB * HH];     // 268 MB precomputed x@Wx^T
__device__ unsigned g_cnt[3];
__device__ unsigned g_gen[3];

// ---- grid barrier (sense-reversing, acquire on waiter) ----
__device__ __forceinline__ void gbar(int idx, unsigned count) {
    __threadfence();
    __syncthreads();
    if (threadIdx.x == 0) {
        volatile unsigned* vg = (volatile unsigned*)&g_gen[idx];
        unsigned g = *vg;
        unsigned old = atomicAdd(&g_cnt[idx], 1u);
        if (old == count - 1) {
            g_cnt[idx] = 0;
            __threadfence();
            *vg = g + 1;
        } else {
            while (*vg == g) { __nanosleep(20); }
            __threadfence();
        }
    }
    __syncthreads();
}

// ---- helpers ----
__device__ __forceinline__ void cpa(float* dst, const float* src) {
    uint32_t d = (uint32_t)__cvta_generic_to_shared(dst);
    asm volatile("cp.async.cg.shared.global [%0], [%1], 16;" :: "r"(d), "l"(src));
}
#define CPCOMMIT() asm volatile("cp.async.commit_group;")
#define CPWAIT(n)  asm volatile("cp.async.wait_group %0;" :: "n"(n))

__device__ __forceinline__ uint32_t f2tf(float f) {
    uint32_t u; asm volatile("cvt.rna.tf32.f32 %0, %1;" : "=r"(u) : "f"(f)); return u;
}
__device__ __forceinline__ void mma8(float* c, uint32_t a0, uint32_t a1,
                                     uint32_t a2, uint32_t a3,
                                     uint32_t b0, uint32_t b1) {
    asm volatile(
        "mma.sync.aligned.m16n8k8.row.col.f32.tf32.tf32.f32 "
        "{%0,%1,%2,%3},{%4,%5,%6,%7},{%8,%9},{%0,%1,%2,%3};"
        : "+f"(c[0]), "+f"(c[1]), "+f"(c[2]), "+f"(c[3])
        : "r"(a0), "r"(a1), "r"(a2), "r"(a3), "r"(b0), "r"(b1));
}

// ---- persistent kernel ----
__global__ void __launch_bounds__(NTHREADS, 1)
SequenceModelPadded_kernel(
    const float* __restrict__ inp,        // (B,T,I)
    const void*  __restrict__ slen_raw,   // (B,) int64 OR int32
    const float* __restrict__ Wx,         // (T,H,I)
    const float* __restrict__ Wh,         // (T,H,H)
    const float* __restrict__ bias,       // (T,H)
    const float* __restrict__ Wout,       // (1,H)
    const float* __restrict__ bout,       // (1,)
    float* __restrict__ out)              // (B,1)
{
    extern __shared__ float sm[];
    __shared__ int s_is64;
    __shared__ int s_perm[256];     // sorted rank -> original batch row
    __shared__ int s_lorig[256];    // original-order lengths
    __shared__ int s_lsorted[256];  // lengths sorted descending (stable)
    __shared__ int s_act[256];      // this half's active-row count per step

    int tid  = threadIdx.x;
    int bx   = blockIdx.x;
    int half = bx >> 6;
    int lh   = bx & 63;
    int nblk = lh >> 2;          // 0..15  (N tile of 64 cols)
    int ks   = lh & 3;           // 0..3   (K split of 256)

    int lane = tid & 31, warp = tid >> 5;
    int wm = warp & 3, wn = warp >> 2;
    int g  = lane >> 2, tg = lane & 3;

    // ---- seq_lengths dtype sniff ----
    if (tid == 0) {
        const unsigned* w = (const unsigned*)slen_raw;
        unsigned z = 0;
        for (int i = 1; i < 256; i += 2) z |= __ldg(&w[i]);
        s_is64 = (z == 0) ? 1 : 0;
    }
    __syncthreads();
    const int is64 = s_is64;

    // ---- sort lengths descending (stable), every CTA locally ----
    {
        int L = is64 ? (int)__ldg(&((const int*)slen_raw)[tid * 2])   // little-endian low word
                     : (int)__ldg(&((const int*)slen_raw)[tid]);
        s_lorig[tid] = L;
        __syncthreads();
        int rank = 0;
        for (int j = 0; j < 256; j++) {
            int Lj = s_lorig[j];
            rank += (Lj > L) || (Lj == L && j < tid);
        }
        s_perm[rank]    = tid;
        s_lsorted[rank] = L;
        __syncthreads();
        // active count per step for OWN half (interleaved ranks: rank = 2*rl + half)
        int a = 0;
        for (int rl = 0; rl < 128; rl++)
            a += (s_lsorted[2 * rl + half] > tid) ? 1 : 0;
        s_act[tid] = a;
        __syncthreads();
    }
    const int hmax = s_lsorted[half];   // loop bound for this half

    // ---- h = 0 (storage rows: half*128 + rl, sorted-interleaved layout) ----
    for (int e = tid; e < 2048; e += NTHREADS) g_h[bx * 2048 + e] = 0.f;

    // ============================================================
    // PROLOGUE: xpart[t, ss(r)] = x[perm[r], t] @ Wx[t]^T, rows sorted,
    // only active rows (r < act_total(t)). ss(r) = (r&1)*128 + (r>>1).
    // ============================================================
    for (int rep = 0; rep < 2; rep++) {
        int t = bx + rep * 128;
        int actp = 0;
        for (int j = 0; j < 256; j++) actp += (s_lsorted[j] > t) ? 1 : 0;
        if (actp == 0) continue;
        int actpL = (actp + 15) & ~15;

        for (int nt = 0; nt < 8; nt++) {
            float acc[4][8][4];
#pragma unroll
            for (int s = 0; s < 4; s++)
#pragma unroll
                for (int u = 0; u < 8; u++)
#pragma unroll
                    for (int q = 0; q < 4; q++) acc[s][u][q] = 0.f;

            {   // chunk 0
                float* pa = sm + F_SA;
                float* pw = sm + F_SW;
#pragma unroll
                for (int it = 0; it < 8; it++) {
                    int v = tid + NTHREADS * it; int row = v >> 3, seg = v & 7;
                    if (row < actpL) {
                        int pr = s_perm[row];
                        cpa(pa + row * 36 + seg * 4,
                            inp + (size_t)pr * (TT * II) + (size_t)t * II + seg * 4);
                    }
                }
#pragma unroll
                for (int it = 0; it < 4; it++) {
                    int v = tid + NTHREADS * it; int row = v >> 3, seg = v & 7;
                    cpa(pw + row * 36 + seg * 4,
                        Wx + ((size_t)t * HH + nt * 128 + row) * II + seg * 4);
                }
                CPCOMMIT();
            }
            for (int ch = 0; ch < 16; ch++) {
                if (ch < 15) {
                    int nb = (ch + 1) & 1;
                    float* pa = sm + F_SA + nb * F_PA_BUF;
                    float* pw = sm + F_SW + nb * F_PW_BUF;
                    int ko = (ch + 1) * 32;
#pragma unroll
                    for (int it = 0; it < 8; it++) {
                        int v = tid + NTHREADS * it; int row = v >> 3, seg = v & 7;
                        if (row < actpL) {
                            int pr = s_perm[row];
                            cpa(pa + row * 36 + seg * 4,
                                inp + (size_t)pr * (TT * II) + (size_t)t * II + ko + seg * 4);
                        }
                    }
#pragma unroll
                    for (int it = 0; it < 4; it++) {
                        int v = tid + NTHREADS * it; int row = v >> 3, seg = v & 7;
                        cpa(pw + row * 36 + seg * 4,
                            Wx + ((size_t)t * HH + nt * 128 + row) * II + ko + seg * 4);
                    }
                    CPCOMMIT();
                    CPWAIT(1);
                } else {
                    CPWAIT(0);
                }
                __syncthreads();
                const float* pa = sm + F_SA + (ch & 1) * F_PA_BUF;
                const float* pw = sm + F_SW + (ch & 1) * F_PW_BUF;
#pragma unroll
                for (int kk = 0; kk < 4; kk++) {
                    uint32_t ua[4][4];
#pragma unroll
                    for (int s = 0; s < 4; s++) {
                        if (wm * 64 + s * 16 < actp) {
                            int base = (wm * 64 + s * 16 + g) * 36 + kk * 8 + tg;
                            ua[s][0] = f2tf(pa[base]);
                            ua[s][1] = f2tf(pa[base + 8 * 36]);
                            ua[s][2] = f2tf(pa[base + 4]);
                            ua[s][3] = f2tf(pa[base + 8 * 36 + 4]);
                        }
                    }
#pragma unroll
                    for (int u = 0; u < 8; u++) {
                        int wb = (wn * 64 + u * 8 + g) * 36 + kk * 8 + tg;
                        uint32_t b0 = f2tf(pw[wb]);
                        uint32_t b1 = f2tf(pw[wb + 4]);
#pragma unroll
                        for (int s = 0; s < 4; s++)
                            if (wm * 64 + s * 16 < actp)
                                mma8(acc[s][u], ua[s][0], ua[s][1], ua[s][2], ua[s][3], b0, b1);
                    }
                }
                __syncthreads();
            }
#pragma unroll
            for (int s = 0; s < 4; s++) {
                if (wm * 64 + s * 16 >= actp) continue;
#pragma unroll
                for (int u = 0; u < 8; u++) {
                    int r0 = wm * 64 + s * 16 + g;
                    int r1 = r0 + 8;
                    int c  = nt * 128 + wn * 64 + u * 8 + 2 * tg;
                    int ss0 = ((r0 & 1) << 7) | (r0 >> 1);
                    int ss1 = ((r1 & 1) << 7) | (r1 >> 1);
                    *(float2*)(g_xpart + ((size_t)t * BB + ss0) * HH + c) =
                        make_float2(acc[s][u][0], acc[s][u][1]);
                    *(float2*)(g_xpart + ((size_t)t * BB + ss1) * HH + c) =
                        make_float2(acc[s][u][2], acc[s][u][3]);
                }
            }
        }
    }

    gbar(2, NCTA);   // xpart + h-init globally visible

    // ============================================================
    // RECURRENT LOOP (t < hmax of this half)
    // ============================================================
    {   // prefetch step-0 W slice + xpart + bias into buffer 0
        float* ws = sm + F_SW;
#pragma unroll
        for (int it = 0; it < 16; it++) {
            int v = tid + NTHREADS * it; int row = v >> 6, seg = v & 63;
            cpa(ws + row * 260 + seg * 4,
                Wh + ((size_t)nblk * 64 + row) * HH + ks * 256 + seg * 4);
        }
        float* xps = sm + F_XP;
#pragma unroll
        for (int it = 0; it < 2; it++) {
            int v = tid + NTHREADS * it; int row = v >> 2, seg = v & 3;
            cpa(xps + row * 16 + seg * 4,
                g_xpart + ((size_t)half * 128 + row) * HH + lh * 16 + seg * 4);
        }
        if (tid < 4)
            cpa(sm + F_BI + tid * 4, bias + lh * 16 + tid * 4);
        CPCOMMIT();
    }

    for (int t = 0; t < hmax; t++) {
        int cur = t & 1;
        int act  = s_act[t];
        int actL = (act + 15) & ~15;

        // drain prefetch group, convert W slice fp32 -> tf32 in place (dedup)
        CPWAIT(0);
        __syncthreads();
        {
            uint32_t* wsu = (uint32_t*)(sm + F_SW + cur * F_SW_BUF);
#pragma unroll
            for (int it = 0; it < 64; it++) {
                int v = tid + NTHREADS * it;          // 0..16383
                int row = v >> 8, col = v & 255;
                int a = row * 260 + col;
                wsu[a] = f2tf(__uint_as_float(wsu[a]));
            }
        }
        __syncthreads();
        const uint32_t* ws = (const uint32_t*)(sm + F_SW + cur * F_SW_BUF);

        float acc[2][4][4];
#pragma unroll
        for (int s = 0; s < 2; s++)
#pragma unroll
            for (int u = 0; u < 4; u++)
#pragma unroll
                for (int q = 0; q < 4; q++) acc[s][u][q] = 0.f;

        {   // A chunk 0 (h already tf32 bits)
            float* pa = sm + F_SA;
            int ko = ks * 256;
#pragma unroll
            for (int it = 0; it < 4; it++) {
                int v = tid + NTHREADS * it; int row = v >> 3, seg = v & 7;
                if (row < actL)
                    cpa(pa + row * 36 + seg * 4,
                        g_h + (size_t)(half * 128 + row) * HH + ko + seg * 4);
            }
            CPCOMMIT();
        }
        for (int j = 0; j < 8; j++) {
            if (j < 7) {
                float* pa = sm + F_SA + ((j + 1) & 1) * F_SA_BUF;
                int ko = ks * 256 + (j + 1) * 32;
#pragma unroll
                for (int it = 0; it < 4; it++) {
                    int v = tid + NTHREADS * it; int row = v >> 3, seg = v & 7;
                    if (row < actL)
                        cpa(pa + row * 36 + seg * 4,
                            g_h + (size_t)(half * 128 + row) * HH + ko + seg * 4);
                }
                CPCOMMIT();
                CPWAIT(1);
            } else {
                CPWAIT(0);
            }
            __syncthreads();
            const uint32_t* pa = (const uint32_t*)(sm + F_SA + (j & 1) * F_SA_BUF);
#pragma unroll
            for (int kk = 0; kk < 4; kk++) {
                uint32_t ua[2][4];
#pragma unroll
                for (int s = 0; s < 2; s++) {
                    if (wm * 32 + s * 16 < act) {
                        int base = (wm * 32 + s * 16 + g) * 36 + kk * 8 + tg;
                        ua[s][0] = pa[base];
                        ua[s][1] = pa[base + 8 * 36];
                        ua[s][2] = pa[base + 4];
                        ua[s][3] = pa[base + 8 * 36 + 4];
                    }
                }
#pragma unroll
                for (int u = 0; u < 4; u++) {
                    int wb = (wn * 32 + u * 8 + g) * 260 + j * 32 + kk * 8 + tg;
                    uint32_t b0 = ws[wb];
                    uint32_t b1 = ws[wb + 4];
#pragma unroll
                    for (int s = 0; s < 2; s++)
                        if (wm * 32 + s * 16 < act)
                            mma8(acc[s][u], ua[s][0], ua[s][1], ua[s][2], ua[s][3], b0, b1);
                }
            }
            __syncthreads();
        }

        {   // prefetch next step's W slice + xpart + bias
            int tn = (t + 1 < TT) ? (t + 1) : (TT - 1);
            int nb = (t + 1) & 1;
            float* wsn = sm + F_SW + nb * F_SW_BUF;
#pragma unroll
            for (int it = 0; it < 16; it++) {
                int v = tid + NTHREADS * it; int row = v >> 6, seg = v & 63;
                cpa(wsn + row * 260 + seg * 4,
                    Wh + ((size_t)tn * HH + nblk * 64 + row) * HH + ks * 256 + seg * 4);
            }
            float* xps = sm + F_XP + nb * F_XP_BUF;
#pragma unroll
            for (int it = 0; it < 2; it++) {
                int v = tid + NTHREADS * it; int row = v >> 2, seg = v & 3;
                cpa(xps + row * 16 + seg * 4,
                    g_xpart + ((size_t)tn * BB + half * 128 + row) * HH + lh * 16 + seg * 4);
            }
            if (tid < 4)
                cpa(sm + F_BI + nb * F_BI_BUF + tid * 4,
                    bias + (size_t)tn * HH + lh * 16 + tid * 4);
            CPCOMMIT();
        }

        {   // store split-K partial (active rows only)
            float* P = g_part + (size_t)(half * 64 + lh) * 8192;
#pragma unroll
            for (int s = 0; s < 2; s++) {
                if (wm * 32 + s * 16 >= act) continue;
#pragma unroll
                for (int u = 0; u < 4; u++) {
                    int r = wm * 32 + s * 16 + g;
                    int c = wn * 32 + u * 8 + 2 * tg;
                    *(float2*)&P[r * 64 + c]       = make_float2(acc[s][u][0], acc[s][u][1]);
                    *(float2*)&P[(r + 8) * 64 + c] = make_float2(acc[s][u][2], acc[s][u][3]);
                }
            }
        }
        gbar(half, HALFC);

        {   // reduce 4 partials + xpart + bias -> tanh -> tf32 -> h (active rows)
            int r = tid >> 1;
            if (r < act) {
                int c8  = (tid & 1) * 8;
                int cg_ = lh * 16 + c8;
                int nb4 = (cg_ >> 6) * 4;
                int cl0 = cg_ & 63;
                float v[8];
#pragma unroll
                for (int q = 0; q < 8; q++) v[q] = 0.f;
#pragma unroll
                for (int ksp = 0; ksp < 4; ksp++) {
                    const float4* p = (const float4*)&g_part[
                        (size_t)(half * 64 + nb4 + ksp) * 8192 + r * 64 + cl0];
                    float4 a = __ldcg(p);
                    float4 b = __ldcg(p + 1);
                    v[0] += a.x; v[1] += a.y; v[2] += a.z; v[3] += a.w;
                    v[4] += b.x; v[5] += b.y; v[6] += b.z; v[7] += b.w;
                }
                const float* xps = sm + F_XP + cur * F_XP_BUF + r * 16 + c8;
                const float* bs  = sm + F_BI + cur * F_BI_BUF + c8;
#pragma unroll
                for (int q = 0; q < 8; q++)
                    v[q] = __uint_as_float(f2tf(tanhf(v[q] + xps[q] + bs[q])));

                float4* hp = (float4*)(g_h + (size_t)(half * 128 + r) * HH + cg_);
                hp[0] = make_float4(v[0], v[1], v[2], v[3]);
                hp[1] = make_float4(v[4], v[5], v[6], v[7]);
            }
        }
        gbar(half, HALFC);
    }

    // ---- output: out[perm[2*rl+half]] = h_storage[half*128+rl] . Wout + bout ----
    float* red = sm;
#pragma unroll
    for (int rr = 0; rr < 2; rr++) {
        int rl = lh * 2 + rr;
        int gr = half * 128 + rl;                 // storage row
        int ob = s_perm[2 * rl + half];           // original batch row
        float p = 0.f;
        for (int c = tid; c < HH; c += NTHREADS)
            p += __ldcg(&g_h[(size_t)gr * HH + c]) * __ldg(&Wout[c]);
        red[tid] = p;
        __syncthreads();
        for (int s = 128; s > 0; s >>= 1) {
            if (tid < s) red[tid] += red[tid + s];
            __syncthreads();
        }
        if (tid == 0) out[ob] = red[0] + __ldg(&bout[0]);
        __syncthreads();
    }
}

extern "C" void kernel_launch(void* const* d_in, const int* in_sizes, int n_in,
                              void* d_out, int out_size) {
    (void)in_sizes; (void)n_in; (void)out_size;
    const float* inp  = (const float*)d_in[0];
    const void*  slen = (const void*)d_in[1];
    const float* Wx   = (const float*)d_in[2];
    const float* Wh   = (const float*)d_in[3];
    const float* bias = (const float*)d_in[4];
    const float* Wout = (const float*)d_in[5];
    const float* bout = (const float*)d_in[6];
    float*       out  = (float*)d_out;

    static int s_attr_done = 0;
    if (!s_attr_done) {
        cudaFuncSetAttribute(SequenceModelPadded_kernel,
                             cudaFuncAttributeMaxDynamicSharedMemorySize, SMEM_BYTES);
        s_attr_done = 1;
    }
    SequenceModelPadded_kernel<<<NCTA, NTHREADS, SMEM_BYTES>>>(
        inp, slen, Wx, Wh, bias, Wout, bout, out);
}

// round 7
// speedup vs baseline: 1.4988x; 1.1606x over previous
#include <cuda_runtime.h>
#include <cstdint>
#include <cstddef>

#define BB 256
#define TT 256
#define II 512
#define HH 1024

#define NTHREADS 256
#define NCTA 128
#define HALFC 64

// ---- loop-phase dynamic smem layout (float offsets) ----
#define L_A      0
#define L_A_BUF  (128*68)            // A stage: 128 x 64, stride 68 (8704 f)
#define L_W      (2*L_A_BUF)         // 17408
#define L_W_BUF  (64*260)            // W slice: 64 x 256, stride 260 (16640 f)
#define L_XP     (L_W + 2*L_W_BUF)   // 50688
#define L_XP_BUF (128*16)
#define L_BI     (L_XP + 2*L_XP_BUF) // 54784
#define L_BI_BUF 16
#define SMEM_FLOATS (L_BI + 2*L_BI_BUF)  // 54816
#define SMEM_BYTES  (SMEM_FLOATS*4)      // 219264 B

// ---- prologue-phase aliased smem layout (temporally disjoint) ----
#define P_A      0
#define P_A_BUF  (256*36)            // 9216
#define P_W      (2*P_A_BUF)         // 18432
#define P_W_BUF  (128*36)            // 4608 (ends 27648 < 54816 ok)

// ---- persistent device state ----
__device__ float    g_h[2][BB * HH];                 // double-buffered h (tf32 bits)
__device__ float    g_part[2][2 * 64 * 8192];        // [parity][(half*64+lh)*8192]
__device__ float    g_xpart[(size_t)TT * BB * HH];   // precomputed x@Wx^T (sorted rows)
__device__ unsigned g_cnt[3];
__device__ unsigned g_gen[3];
__device__ unsigned g_pflag[2][16];                  // partial producers per nblk
__device__ unsigned g_hflag[2][4];                   // h writers per ks-group

// ---- grid barrier (used twice: after prologue, before output) ----
__device__ __forceinline__ void gbar(int idx, unsigned count) {
    __threadfence();
    __syncthreads();
    if (threadIdx.x == 0) {
        volatile unsigned* vg = (volatile unsigned*)&g_gen[idx];
        unsigned g = *vg;
        unsigned old = atomicAdd(&g_cnt[idx], 1u);
        if (old == count - 1) {
            g_cnt[idx] = 0;
            __threadfence();
            *vg = g + 1;
        } else {
            while (*vg == g) {}
            __threadfence();
        }
    }
    __syncthreads();
}

// ---- flag sync: release-arrive / acquire-wait on monotonic counters ----
__device__ __forceinline__ void arrive(unsigned* f) {
    __threadfence();
    __syncthreads();
    if (threadIdx.x == 0) atomicAdd(f, 1u);
}
__device__ __forceinline__ void waitflag(unsigned* f, unsigned target) {
    __syncthreads();
    if (threadIdx.x == 0) {
        volatile unsigned* vf = (volatile unsigned*)f;
        while (*vf < target) {}
        __threadfence();
    }
    __syncthreads();
}

// ---- helpers ----
__device__ __forceinline__ void cpa(float* dst, const float* src) {
    uint32_t d = (uint32_t)__cvta_generic_to_shared(dst);
    asm volatile("cp.async.cg.shared.global [%0], [%1], 16;" :: "r"(d), "l"(src));
}
#define CPCOMMIT() asm volatile("cp.async.commit_group;")
#define CPWAIT(n)  asm volatile("cp.async.wait_group %0;" :: "n"(n))

__device__ __forceinline__ uint32_t f2tf(float f) {
    uint32_t u; asm volatile("cvt.rna.tf32.f32 %0, %1;" : "=r"(u) : "f"(f)); return u;
}
__device__ __forceinline__ void mma8(float* c, uint32_t a0, uint32_t a1,
                                     uint32_t a2, uint32_t a3,
                                     uint32_t b0, uint32_t b1) {
    asm volatile(
        "mma.sync.aligned.m16n8k8.row.col.f32.tf32.tf32.f32 "
        "{%0,%1,%2,%3},{%4,%5,%6,%7},{%8,%9},{%0,%1,%2,%3};"
        : "+f"(c[0]), "+f"(c[1]), "+f"(c[2]), "+f"(c[3])
        : "r"(a0), "r"(a1), "r"(a2), "r"(a3), "r"(b0), "r"(b1));
}

// ---- persistent kernel ----
__global__ void __launch_bounds__(NTHREADS, 1)
SequenceModelPadded_kernel(
    const float* __restrict__ inp,        // (B,T,I)
    const void*  __restrict__ slen_raw,   // (B,) int64 OR int32
    const float* __restrict__ Wx,         // (T,H,I)
    const float* __restrict__ Wh,         // (T,H,H)
    const float* __restrict__ bias,       // (T,H)
    const float* __restrict__ Wout,       // (1,H)
    const float* __restrict__ bout,       // (1,)
    float* __restrict__ out)              // (B,1)
{
    extern __shared__ float sm[];
    __shared__ int s_is64;
    __shared__ int s_perm[256];
    __shared__ int s_lorig[256];
    __shared__ int s_lsorted[256];
    __shared__ int s_act[256];

    int tid  = threadIdx.x;
    int bx   = blockIdx.x;
    int half = bx >> 6;
    int lh   = bx & 63;
    int nblk = lh >> 2;          // 0..15 (N tile of 64 cols)
    int ks   = lh & 3;           // 0..3  (K split of 256)

    int lane = tid & 31, warp = tid >> 5;
    int wm = warp & 3, wn = warp >> 2;
    int g  = lane >> 2, tg = lane & 3;

    // ---- seq_lengths dtype sniff ----
    if (tid == 0) {
        const unsigned* w = (const unsigned*)slen_raw;
        unsigned z = 0;
        for (int i = 1; i < 256; i += 2) z |= __ldg(&w[i]);
        s_is64 = (z == 0) ? 1 : 0;
    }
    __syncthreads();
    const int is64 = s_is64;

    // ---- stable sort of lengths (descending), local per CTA ----
    {
        int L = is64 ? (int)__ldg(&((const int*)slen_raw)[tid * 2])
                     : (int)__ldg(&((const int*)slen_raw)[tid]);
        s_lorig[tid] = L;
        __syncthreads();
        int rank = 0;
        for (int j = 0; j < 256; j++) {
            int Lj = s_lorig[j];
            rank += (Lj > L) || (Lj == L && j < tid);
        }
        s_perm[rank]    = tid;
        s_lsorted[rank] = L;
        __syncthreads();
        int a = 0;
        for (int rl = 0; rl < 128; rl++)
            a += (s_lsorted[2 * rl + half] > tid) ? 1 : 0;
        s_act[tid] = a;
        __syncthreads();
    }
    const int hmax = s_lsorted[half];

    // ---- zero BOTH h buffers ----
    for (int e = tid; e < 2048; e += NTHREADS) {
        g_h[0][bx * 2048 + e] = 0.f;
        g_h[1][bx * 2048 + e] = 0.f;
    }

    // ---- reset flags (launch-safe; visible to all after gbar below) ----
    if (bx == 0 && tid == 0) {
        for (int i = 0; i < 16; i++) { g_pflag[0][i] = 0; g_pflag[1][i] = 0; }
        for (int i = 0; i < 4;  i++) { g_hflag[0][i] = 0; g_hflag[1][i] = 0; }
    }

    // ============================================================
    // PROLOGUE: xpart[t, ss(r)] = x[perm[r], t] @ Wx[t]^T (act-scaled)
    // ss(r) = (r&1)*128 + (r>>1) interleaves ranks across halves.
    // ============================================================
    for (int rep = 0; rep < 2; rep++) {
        int t = bx + rep * 128;
        int actp = 0;
        for (int j = 0; j < 256; j++) actp += (s_lsorted[j] > t) ? 1 : 0;
        if (actp == 0) continue;
        int actpL = (actp + 15) & ~15;

        for (int nt = 0; nt < 8; nt++) {
            float acc[4][8][4];
#pragma unroll
            for (int s = 0; s < 4; s++)
#pragma unroll
                for (int u = 0; u < 8; u++)
#pragma unroll
                    for (int q = 0; q < 4; q++) acc[s][u][q] = 0.f;

            {   // chunk 0
                float* pa = sm + P_A;
                float* pw = sm + P_W;
#pragma unroll
                for (int it = 0; it < 8; it++) {
                    int v = tid + NTHREADS * it; int row = v >> 3, seg = v & 7;
                    if (row < actpL) {
                        int pr = s_perm[row];
                        cpa(pa + row * 36 + seg * 4,
                            inp + (size_t)pr * (TT * II) + (size_t)t * II + seg * 4);
                    }
                }
#pragma unroll
                for (int it = 0; it < 4; it++) {
                    int v = tid + NTHREADS * it; int row = v >> 3, seg = v & 7;
                    cpa(pw + row * 36 + seg * 4,
                        Wx + ((size_t)t * HH + nt * 128 + row) * II + seg * 4);
                }
                CPCOMMIT();
            }
            for (int ch = 0; ch < 16; ch++) {
                if (ch < 15) {
                    int nb = (ch + 1) & 1;
                    float* pa = sm + P_A + nb * P_A_BUF;
                    float* pw = sm + P_W + nb * P_W_BUF;
                    int ko = (ch + 1) * 32;
#pragma unroll
                    for (int it = 0; it < 8; it++) {
                        int v = tid + NTHREADS * it; int row = v >> 3, seg = v & 7;
                        if (row < actpL) {
                            int pr = s_perm[row];
                            cpa(pa + row * 36 + seg * 4,
                                inp + (size_t)pr * (TT * II) + (size_t)t * II + ko + seg * 4);
                        }
                    }
#pragma unroll
                    for (int it = 0; it < 4; it++) {
                        int v = tid + NTHREADS * it; int row = v >> 3, seg = v & 7;
                        cpa(pw + row * 36 + seg * 4,
                            Wx + ((size_t)t * HH + nt * 128 + row) * II + ko + seg * 4);
                    }
                    CPCOMMIT();
                    CPWAIT(1);
                } else {
                    CPWAIT(0);
                }
                __syncthreads();
                const float* pa = sm + P_A + (ch & 1) * P_A_BUF;
                const float* pw = sm + P_W + (ch & 1) * P_W_BUF;
#pragma unroll
                for (int kk = 0; kk < 4; kk++) {
                    uint32_t ua[4][4];
#pragma unroll
                    for (int s = 0; s < 4; s++) {
                        if (wm * 64 + s * 16 < actp) {
                            int base = (wm * 64 + s * 16 + g) * 36 + kk * 8 + tg;
                            ua[s][0] = f2tf(pa[base]);
                            ua[s][1] = f2tf(pa[base + 8 * 36]);
                            ua[s][2] = f2tf(pa[base + 4]);
                            ua[s][3] = f2tf(pa[base + 8 * 36 + 4]);
                        }
                    }
#pragma unroll
                    for (int u = 0; u < 8; u++) {
                        int wb = (wn * 64 + u * 8 + g) * 36 + kk * 8 + tg;
                        uint32_t b0 = f2tf(pw[wb]);
                        uint32_t b1 = f2tf(pw[wb + 4]);
#pragma unroll
                        for (int s = 0; s < 4; s++)
                            if (wm * 64 + s * 16 < actp)
                                mma8(acc[s][u], ua[s][0], ua[s][1], ua[s][2], ua[s][3], b0, b1);
                    }
                }
                __syncthreads();
            }
#pragma unroll
            for (int s = 0; s < 4; s++) {
                if (wm * 64 + s * 16 >= actp) continue;
#pragma unroll
                for (int u = 0; u < 8; u++) {
                    int r0 = wm * 64 + s * 16 + g;
                    int r1 = r0 + 8;
                    int c  = nt * 128 + wn * 64 + u * 8 + 2 * tg;
                    int ss0 = ((r0 & 1) << 7) | (r0 >> 1);
                    int ss1 = ((r1 & 1) << 7) | (r1 >> 1);
                    *(float2*)(g_xpart + ((size_t)t * BB + ss0) * HH + c) =
                        make_float2(acc[s][u][0], acc[s][u][1]);
                    *(float2*)(g_xpart + ((size_t)t * BB + ss1) * HH + c) =
                        make_float2(acc[s][u][2], acc[s][u][3]);
                }
            }
        }
    }

    gbar(2, NCTA);   // xpart + h-init + flag reset globally visible

    // ============================================================
    // RECURRENT LOOP — flag-synced, no global barriers
    // ============================================================
    {   // prefetch step-0 W slice + xpart + bias into buffer 0
        float* ws = sm + L_W;
#pragma unroll
        for (int it = 0; it < 16; it++) {
            int v = tid + NTHREADS * it; int row = v >> 6, seg = v & 63;
            cpa(ws + row * 260 + seg * 4,
                Wh + ((size_t)nblk * 64 + row) * HH + ks * 256 + seg * 4);
        }
        float* xps = sm + L_XP;
#pragma unroll
        for (int it = 0; it < 2; it++) {
            int v = tid + NTHREADS * it; int row = v >> 2, seg = v & 3;
            cpa(xps + row * 16 + seg * 4,
                g_xpart + ((size_t)half * 128 + row) * HH + lh * 16 + seg * 4);
        }
        if (tid < 4)
            cpa(sm + L_BI + tid * 4, bias + lh * 16 + tid * 4);
        CPCOMMIT();
    }

    for (int t = 0; t < hmax; t++) {
        int cur = t & 1;
        int nxt = cur ^ 1;
        int act      = s_act[t];
        int act_prev = (t == 0) ? 128 : s_act[t - 1];
        int actL = (act + 15) & ~15;

        // drain prefetch; convert W slice to tf32 in place (dedup'd)
        CPWAIT(0);
        __syncthreads();
        {
            uint32_t* wsu = (uint32_t*)(sm + L_W + cur * L_W_BUF);
#pragma unroll
            for (int it = 0; it < 64; it++) {
                int v = tid + NTHREADS * it;
                int row = v >> 8, col = v & 255;
                int a = row * 260 + col;
                wsu[a] = f2tf(__uint_as_float(wsu[a]));
            }
        }
        __syncthreads();
        const uint32_t* ws = (const uint32_t*)(sm + L_W + cur * L_W_BUF);

        // wait until my h K-slice (cols [256ks,+256)) for step t is ready
        waitflag(&g_hflag[half][ks], 16u * (unsigned)t);

        const float* hbuf = g_h[cur];

        float acc[2][4][4];
#pragma unroll
        for (int s = 0; s < 2; s++)
#pragma unroll
            for (int u = 0; u < 4; u++)
#pragma unroll
                for (int q = 0; q < 4; q++) acc[s][u][q] = 0.f;

        {   // A stage 0 (64-wide)
            float* pa = sm + L_A;
            int ko = ks * 256;
#pragma unroll
            for (int it = 0; it < 8; it++) {
                int v = tid + NTHREADS * it; int row = v >> 4, seg = v & 15;
                if (row < actL)
                    cpa(pa + row * 68 + seg * 4,
                        hbuf + (size_t)(half * 128 + row) * HH + ko + seg * 4);
            }
            CPCOMMIT();
        }
        for (int j = 0; j < 4; j++) {
            if (j < 3) {
                float* pa = sm + L_A + ((j + 1) & 1) * L_A_BUF;
                int ko = ks * 256 + (j + 1) * 64;
#pragma unroll
                for (int it = 0; it < 8; it++) {
                    int v = tid + NTHREADS * it; int row = v >> 4, seg = v & 15;
                    if (row < actL)
                        cpa(pa + row * 68 + seg * 4,
                            hbuf + (size_t)(half * 128 + row) * HH + ko + seg * 4);
                }
                CPCOMMIT();
                CPWAIT(1);
            } else {
                CPWAIT(0);
            }
            __syncthreads();
            const uint32_t* pa = (const uint32_t*)(sm + L_A + (j & 1) * L_A_BUF);
#pragma unroll
            for (int kk = 0; kk < 8; kk++) {
                uint32_t ua[2][4];
#pragma unroll
                for (int s = 0; s < 2; s++) {
                    if (wm * 32 + s * 16 < act) {
                        int base = (wm * 32 + s * 16 + g) * 68 + kk * 8 + tg;
                        ua[s][0] = pa[base];
                        ua[s][1] = pa[base + 8 * 68];
                        ua[s][2] = pa[base + 4];
                        ua[s][3] = pa[base + 8 * 68 + 4];
                    }
                }
#pragma unroll
                for (int u = 0; u < 4; u++) {
                    int wb = (wn * 32 + u * 8 + g) * 260 + j * 64 + kk * 8 + tg;
                    uint32_t b0 = ws[wb];
                    uint32_t b1 = ws[wb + 4];
#pragma unroll
                    for (int s = 0; s < 2; s++)
                        if (wm * 32 + s * 16 < act)
                            mma8(acc[s][u], ua[s][0], ua[s][1], ua[s][2], ua[s][3], b0, b1);
                }
            }
            __syncthreads();
        }

        {   // prefetch next step's W slice + xpart + bias
            int tn = (t + 1 < TT) ? (t + 1) : (TT - 1);
            float* wsn = sm + L_W + nxt * L_W_BUF;
#pragma unroll
            for (int it = 0; it < 16; it++) {
                int v = tid + NTHREADS * it; int row = v >> 6, seg = v & 63;
                cpa(wsn + row * 260 + seg * 4,
                    Wh + ((size_t)tn * HH + nblk * 64 + row) * HH + ks * 256 + seg * 4);
            }
            float* xps = sm + L_XP + nxt * L_XP_BUF;
#pragma unroll
            for (int it = 0; it < 2; it++) {
                int v = tid + NTHREADS * it; int row = v >> 2, seg = v & 3;
                cpa(xps + row * 16 + seg * 4,
                    g_xpart + ((size_t)tn * BB + half * 128 + row) * HH + lh * 16 + seg * 4);
            }
            if (tid < 4)
                cpa(sm + L_BI + nxt * L_BI_BUF + tid * 4,
                    bias + (size_t)tn * HH + lh * 16 + tid * 4);
            CPCOMMIT();
        }

        {   // store split-K partial (active rows) into parity buffer
            float* P = g_part[cur] + (size_t)(half * 64 + lh) * 8192;
#pragma unroll
            for (int s = 0; s < 2; s++) {
                if (wm * 32 + s * 16 >= act) continue;
#pragma unroll
                for (int u = 0; u < 4; u++) {
                    int r = wm * 32 + s * 16 + g;
                    int c = wn * 32 + u * 8 + 2 * tg;
                    *(float2*)&P[r * 64 + c]       = make_float2(acc[s][u][0], acc[s][u][1]);
                    *(float2*)&P[(r + 8) * 64 + c] = make_float2(acc[s][u][2], acc[s][u][3]);
                }
            }
        }
        arrive(&g_pflag[half][nblk]);

        // wait for the 4 producers of MY col range (nblk = lh>>2)
        waitflag(&g_pflag[half][lh >> 2], 4u * (unsigned)(t + 1));

        {   // reduce 4 partials + xpart + bias -> tanh -> tf32 -> h[nxt]
            int r = tid >> 1;
            int c8  = (tid & 1) * 8;
            int cg_ = lh * 16 + c8;
            if (r < act) {
                int nb4 = (cg_ >> 6) * 4;
                int cl0 = cg_ & 63;
                float v[8];
#pragma unroll
                for (int q = 0; q < 8; q++) v[q] = 0.f;
#pragma unroll
                for (int ksp = 0; ksp < 4; ksp++) {
                    const float4* p = (const float4*)&g_part[cur][
                        (size_t)(half * 64 + nb4 + ksp) * 8192 + r * 64 + cl0];
                    float4 a = __ldcg(p);
                    float4 b = __ldcg(p + 1);
                    v[0] += a.x; v[1] += a.y; v[2] += a.z; v[3] += a.w;
                    v[4] += b.x; v[5] += b.y; v[6] += b.z; v[7] += b.w;
                }
                const float* xps = sm + L_XP + cur * L_XP_BUF + r * 16 + c8;
                const float* bs  = sm + L_BI + cur * L_BI_BUF + c8;
#pragma unroll
                for (int q = 0; q < 8; q++)
                    v[q] = __uint_as_float(f2tf(tanhf(v[q] + xps[q] + bs[q])));

                float4* hp = (float4*)(g_h[nxt] + (size_t)(half * 128 + r) * HH + cg_);
                hp[0] = make_float4(v[0], v[1], v[2], v[3]);
                hp[1] = make_float4(v[4], v[5], v[6], v[7]);
            } else if (r < act_prev) {
                // row froze this step: propagate current h into the other buffer
                const float4* src = (const float4*)(g_h[cur] + (size_t)(half * 128 + r) * HH + cg_);
                float4* dst = (float4*)(g_h[nxt] + (size_t)(half * 128 + r) * HH + cg_);
                dst[0] = __ldcg(src);
                dst[1] = __ldcg(src + 1);
            }
        }
        arrive(&g_hflag[half][lh >> 4]);
    }

    CPWAIT(0);
    gbar(half, HALFC);   // all h writes of this half visible

    // ---- output: out[perm[2*rl+half]] = h . Wout + bout ----
    const float* hfin = g_h[hmax & 1];
    float* red = sm;
#pragma unroll
    for (int rr = 0; rr < 2; rr++) {
        int rl = lh * 2 + rr;
        int gr = half * 128 + rl;
        int ob = s_perm[2 * rl + half];
        float p = 0.f;
        for (int c = tid; c < HH; c += NTHREADS)
            p += __ldcg(&hfin[(size_t)gr * HH + c]) * __ldg(&Wout[c]);
        red[tid] = p;
        __syncthreads();
        for (int s = 128; s > 0; s >>= 1) {
            if (tid < s) red[tid] += red[tid + s];
            __syncthreads();
        }
        if (tid == 0) out[ob] = red[0] + __ldg(&bout[0]);
        __syncthreads();
    }
}

extern "C" void kernel_launch(void* const* d_in, const int* in_sizes, int n_in,
                              void* d_out, int out_size) {
    (void)in_sizes; (void)n_in; (void)out_size;
    const float* inp  = (const float*)d_in[0];
    const void*  slen = (const void*)d_in[1];
    const float* Wx   = (const float*)d_in[2];
    const float* Wh   = (const float*)d_in[3];
    const float* bias = (const float*)d_in[4];
    const float* Wout = (const float*)d_in[5];
    const float* bout = (const float*)d_in[6];
    float*       out  = (float*)d_out;

    static int s_attr_done = 0;
    if (!s_attr_done) {
        cudaFuncSetAttribute(SequenceModelPadded_kernel,
                             cudaFuncAttributeMaxDynamicSharedMemorySize, SMEM_BYTES);
        s_attr_done = 1;
    }
    SequenceModelPadded_kernel<<<NCTA, NTHREADS, SMEM_BYTES>>>(
        inp, slen, Wx, Wh, bias, Wout, bout, out);
}